// round 5
// baseline (speedup 1.0000x reference)
#include <cuda_runtime.h>
#include <cuda_bf16.h>
#include <cstdint>
#include <cstddef>

#define GXD 480
#define GYD 360
#define NSEG (GXD*GYD)
#define NHD 32
#define MAXN 131072
#define EPSF 1e-5f

// ---------------- scratch (device globals; no allocation allowed) ----------------
__device__ float    g_y1[(size_t)MAXN * 64];
__device__ float    g_y2[(size_t)MAXN * 128];
__device__ float    g_y3[(size_t)MAXN * 256];
__device__ unsigned g_seg[(size_t)NSEG * 512];
__device__ int      g_occ[NSEG];
__device__ float    g_sum[512];
__device__ float    g_sq[512];
__device__ float    g_scale[512];
__device__ float    g_shift[512];
// transposed weights [CO][K]
__device__ float    g_wt2[64 * 128];
__device__ float    g_wt3[128 * 256];
__device__ float    g_wt4[256 * 512];
__device__ float    g_wt5[512 * 32];

// order-preserving float<->uint mapping for atomicMax-based segment max
__device__ __forceinline__ unsigned fenc(float f) {
    unsigned u = __float_as_uint(f);
    return (u & 0x80000000u) ? ~u : (u | 0x80000000u);
}
__device__ __forceinline__ float fdec(unsigned k) {
    unsigned u = (k & 0x80000000u) ? (k & 0x7FFFFFFFu) : ~k;
    return __uint_as_float(u);
}

__device__ __forceinline__ unsigned packbf(float x, float y) {
    __nv_bfloat162 t = __floats2bfloat162_rn(x, y);
    return *(unsigned*)&t;
}
// split (x,y) into hi-pair and lo-pair (residual) bf16x2 words
__device__ __forceinline__ void split2(float x, float y, unsigned& hi, unsigned& lo) {
    __nv_bfloat16 hx = __float2bfloat16_rn(x);
    __nv_bfloat16 hy = __float2bfloat16_rn(y);
    float rx = x - __bfloat162float(hx);
    float ry = y - __bfloat162float(hy);
    hi = packbf(__bfloat162float(hx), __bfloat162float(hy));
    lo = packbf(rx, ry);
}

__device__ __forceinline__ void mma_bf16(float c[4], const unsigned a[4], const unsigned b[2]) {
    asm volatile(
        "mma.sync.aligned.m16n8k16.row.col.f32.bf16.bf16.f32 "
        "{%0,%1,%2,%3}, {%4,%5,%6,%7}, {%8,%9}, {%0,%1,%2,%3};"
        : "+f"(c[0]), "+f"(c[1]), "+f"(c[2]), "+f"(c[3])
        : "r"(a[0]), "r"(a[1]), "r"(a[2]), "r"(a[3]), "r"(b[0]), "r"(b[1]));
}

// permuted u32-column within an 8-col (k16) group: kp and kp+4 become adjacent
__device__ __forceinline__ int pcol(int c) {   // c in [0,16): group g=c>>3, cl=c&7
    int g = c >> 3, cl = c & 7;
    return g * 8 + ((cl < 4) ? (2 * cl) : (2 * (cl - 4) + 1));
}

// ---------------- clear scratch for one sample ----------------
__global__ void clear_kernel() {
    size_t i = (size_t)blockIdx.x * blockDim.x + threadIdx.x;
    size_t stride = (size_t)gridDim.x * blockDim.x;
    const size_t n4 = (size_t)NSEG * 512 / 4;
    uint4 z = {0u, 0u, 0u, 0u};
    uint4* s4 = (uint4*)g_seg;
    for (size_t j = i; j < n4; j += stride) s4[j] = z;
    for (size_t j = i; j < (size_t)NSEG; j += stride) g_occ[j] = 0;
    if (i < 512) { g_sum[i] = 0.f; g_sq[i] = 0.f; }
}

// ---------------- weight transpose: WT[c][k] = W[k][c] ----------------
__global__ void transpose_w(const float* __restrict__ W, float* __restrict__ WT, int K, int CO) {
    int i = blockIdx.x * 256 + threadIdx.x;
    if (i < K * CO) {
        int k = i / CO, c = i % CO;
        WT[(size_t)c * K + k] = W[i];
    }
}

// ---------------- per-column sum / sumsq (C must divide blockDim.x) ----------------
__global__ void colstats_kernel(const float* __restrict__ X, int n, int C,
                                float* __restrict__ gsum, float* __restrict__ gsq) {
    int tid = threadIdx.x;
    int nt = blockDim.x;
    int col = tid % C;
    int rpb = nt / C;
    int sub = tid / C;
    float s = 0.f, q = 0.f;
    for (long long r = (long long)blockIdx.x * rpb + sub; r < n; r += (long long)gridDim.x * rpb) {
        float v = X[r * (long long)C + col];
        s += v; q += v * v;
    }
    __shared__ float ss[256];
    __shared__ float qq[256];
    ss[tid] = s; qq[tid] = q;
    __syncthreads();
    if (sub == 0) {
        for (int t = tid + C; t < nt; t += C) { s += ss[t]; q += qq[t]; }
        atomicAdd(&gsum[col], s);
        atomicAdd(&gsq[col], q);
    }
}

// ---------------- stats -> (scale, shift) ----------------
__global__ void finalize_kernel(const float* __restrict__ sum, const float* __restrict__ sq,
                                const float* __restrict__ g, const float* __restrict__ b,
                                float* __restrict__ scale, float* __restrict__ shift,
                                int C, float invn) {
    int i = blockIdx.x * blockDim.x + threadIdx.x;
    if (i < C) {
        float m = sum[i] * invn;
        float v = sq[i] * invn - m * m;
        float sc = g[i] * rsqrtf(v + EPSF);
        scale[i] = sc;
        shift[i] = b[i] - m * sc;
    }
}

// ---------------- layer1: [n,7] -> [n,64], thread-per-point, fp32 ----------------
__global__ void __launch_bounds__(256) gemm1_kernel(
    const float* __restrict__ X, const float* __restrict__ sc, const float* __restrict__ sh,
    const float* __restrict__ W, const float* __restrict__ bias,
    float* __restrict__ Y, int n) {
    __shared__ float Ws[7][64];
    __shared__ float bs[64];
    __shared__ float scs[7], shs[7];
    int tid = threadIdx.x;
    for (int i = tid; i < 448; i += 256) Ws[i / 64][i % 64] = W[i];
    if (tid < 64) bs[tid] = bias[tid];
    if (tid < 7) { scs[tid] = sc[tid]; shs[tid] = sh[tid]; }
    __syncthreads();
    int r = blockIdx.x * 256 + tid;
    if (r >= n) return;
    float a[7];
#pragma unroll
    for (int f = 0; f < 7; f++) a[f] = X[(size_t)r * 7 + f] * scs[f] + shs[f];  // bn0, no relu
    float acc[64];
#pragma unroll
    for (int c = 0; c < 64; c++) {
        float v = bs[c];
#pragma unroll
        for (int f = 0; f < 7; f++) v += a[f] * Ws[f][c];
        acc[c] = v;
    }
    float4* yo = (float4*)&Y[(size_t)r * 64];
#pragma unroll
    for (int c4 = 0; c4 < 16; c4++)
        yo[c4] = make_float4(acc[c4 * 4], acc[c4 * 4 + 1], acc[c4 * 4 + 2], acc[c4 * 4 + 3]);
}

// ================= bf16x3 MMA GEMM =================
// Y[n,CO] = relu(X*scale+shift)[n,K] @ W[K,CO] + b     (W given transposed: WT[CO][K])
// BM=128 BN=128 BK=32. 256 threads = 8 warps (2 m x 4 n), warp tile 64x32.
// EPI=0: store Y.  EPI=1: atomicMax scatter into segment buffer (layer 4).
#define ASTR 20
#define BSTR 20
template <int EPI>
__global__ void __launch_bounds__(256) gemm_bf16x3(
    const float* __restrict__ X, int K,
    const float* __restrict__ scale, const float* __restrict__ shift,
    const float* __restrict__ WT, int CO, const float* __restrict__ bias,
    float* __restrict__ Y, const int* __restrict__ xy, unsigned* __restrict__ seg, int n) {
    __shared__ unsigned Ahi[128 * ASTR];
    __shared__ unsigned Alo[128 * ASTR];
    __shared__ unsigned Bhi[128 * BSTR];
    __shared__ unsigned Blo[128 * BSTR];
    __shared__ int ids[128];
    extern __shared__ float dyn[];
    float* scs = dyn;
    float* shs = dyn + K;

    const int tid = threadIdx.x;
    const int lane = tid & 31;
    const int wid = tid >> 5;
    const int row0 = blockIdx.y * 128;
    const int col0 = blockIdx.x * 128;
    const int m0 = (wid & 1) * 64;
    const int n0 = (wid >> 1) * 32;
    const int kp = lane & 3;
    const int lg = lane >> 2;

    for (int i = tid; i < K; i += 256) { scs[i] = scale[i]; shs[i] = shift[i]; }
    if (EPI == 1 && tid < 128) {
        int gr = row0 + tid;
        ids[tid] = (gr < n) ? (xy[(size_t)gr * 2] * GYD + xy[(size_t)gr * 2 + 1]) : 0;
    }
    __syncthreads();

    float acc[4][4][4] = {};
    float4 pa[4], pb[4];

    // prefetch chunk 0
#pragma unroll
    for (int l = 0; l < 4; l++) {
        int idx = tid + l * 256;
        int row = idx >> 3, k4 = (idx & 7) * 4;
        int gr = row0 + row;
        pa[l] = (gr < n) ? *(const float4*)&X[(size_t)gr * K + k4] : make_float4(0.f, 0.f, 0.f, 0.f);
        int c = idx >> 3;
        pb[l] = *(const float4*)&WT[(size_t)(col0 + c) * K + k4];
    }

    for (int k0 = 0; k0 < K; k0 += 32) {
        // store prefetched tiles to smem (bn+relu+split for A, split for B)
#pragma unroll
        for (int l = 0; l < 4; l++) {
            int idx = tid + l * 256;
            int row = idx >> 3, k4 = (idx & 7) * 4;
            float4 v = pa[l];
            float x0 = fmaxf(v.x * scs[k0 + k4 + 0] + shs[k0 + k4 + 0], 0.f);
            float x1 = fmaxf(v.y * scs[k0 + k4 + 1] + shs[k0 + k4 + 1], 0.f);
            float x2 = fmaxf(v.z * scs[k0 + k4 + 2] + shs[k0 + k4 + 2], 0.f);
            float x3 = fmaxf(v.w * scs[k0 + k4 + 3] + shs[k0 + k4 + 3], 0.f);
            unsigned h0, l0, h1, l1;
            split2(x0, x1, h0, l0);
            split2(x2, x3, h1, l1);
            int c0 = k4 >> 1;
            Ahi[row * ASTR + pcol(c0)] = h0;
            Ahi[row * ASTR + pcol(c0 + 1)] = h1;
            Alo[row * ASTR + pcol(c0)] = l0;
            Alo[row * ASTR + pcol(c0 + 1)] = l1;
            float4 w = pb[l];
            split2(w.x, w.y, h0, l0);
            split2(w.z, w.w, h1, l1);
            Bhi[row * BSTR + pcol(c0)] = h0;
            Bhi[row * BSTR + pcol(c0 + 1)] = h1;
            Blo[row * BSTR + pcol(c0)] = l0;
            Blo[row * BSTR + pcol(c0 + 1)] = l1;
        }
        __syncthreads();

        // prefetch next chunk (overlaps with MMA below)
        if (k0 + 32 < K) {
#pragma unroll
            for (int l = 0; l < 4; l++) {
                int idx = tid + l * 256;
                int row = idx >> 3, k4 = (idx & 7) * 4;
                int gr = row0 + row;
                pa[l] = (gr < n) ? *(const float4*)&X[(size_t)gr * K + k0 + 32 + k4]
                                 : make_float4(0.f, 0.f, 0.f, 0.f);
                pb[l] = *(const float4*)&WT[(size_t)(col0 + row) * K + k0 + 32 + k4];
            }
        }

#pragma unroll
        for (int s = 0; s < 2; s++) {
            unsigned ahi[4][4], alo[4][4];
#pragma unroll
            for (int mf = 0; mf < 4; mf++) {
                int r = m0 + mf * 16 + lg;
                uint2 h0 = *(const uint2*)&Ahi[r * ASTR + s * 8 + 2 * kp];
                uint2 h1 = *(const uint2*)&Ahi[(r + 8) * ASTR + s * 8 + 2 * kp];
                ahi[mf][0] = h0.x; ahi[mf][1] = h1.x; ahi[mf][2] = h0.y; ahi[mf][3] = h1.y;
                uint2 q0 = *(const uint2*)&Alo[r * ASTR + s * 8 + 2 * kp];
                uint2 q1 = *(const uint2*)&Alo[(r + 8) * ASTR + s * 8 + 2 * kp];
                alo[mf][0] = q0.x; alo[mf][1] = q1.x; alo[mf][2] = q0.y; alo[mf][3] = q1.y;
            }
            unsigned bhi[4][2], blo[4][2];
#pragma unroll
            for (int nf = 0; nf < 4; nf++) {
                int c = n0 + nf * 8 + lg;
                uint2 h = *(const uint2*)&Bhi[c * BSTR + s * 8 + 2 * kp];
                bhi[nf][0] = h.x; bhi[nf][1] = h.y;
                uint2 q = *(const uint2*)&Blo[c * BSTR + s * 8 + 2 * kp];
                blo[nf][0] = q.x; blo[nf][1] = q.y;
            }
#pragma unroll
            for (int mf = 0; mf < 4; mf++)
#pragma unroll
                for (int nf = 0; nf < 4; nf++) {
                    mma_bf16(acc[mf][nf], ahi[mf], bhi[nf]);
                    mma_bf16(acc[mf][nf], ahi[mf], blo[nf]);
                    mma_bf16(acc[mf][nf], alo[mf], bhi[nf]);
                }
        }
        __syncthreads();
    }

    // epilogue: c0=(r,c) c1=(r,c+1) c2=(r+8,c) c3=(r+8,c+1)
#pragma unroll
    for (int mf = 0; mf < 4; mf++) {
#pragma unroll
        for (int nf = 0; nf < 4; nf++) {
            int lr = m0 + mf * 16 + lg;
            int col = col0 + n0 + nf * 8 + 2 * kp;
            float bc0 = __ldg(&bias[col]);
            float bc1 = __ldg(&bias[col + 1]);
            if (EPI == 0) {
                int gr = row0 + lr;
                if (gr < n)
                    *(float2*)&Y[(size_t)gr * CO + col] =
                        make_float2(acc[mf][nf][0] + bc0, acc[mf][nf][1] + bc1);
                gr += 8;
                if (gr < n)
                    *(float2*)&Y[(size_t)gr * CO + col] =
                        make_float2(acc[mf][nf][2] + bc0, acc[mf][nf][3] + bc1);
            } else {
                int gr = row0 + lr;
                if (gr < n) {
                    unsigned* srow = seg + (size_t)ids[lr] * 512;
                    atomicMax(&srow[col], fenc(acc[mf][nf][0] + bc0));
                    atomicMax(&srow[col + 1], fenc(acc[mf][nf][1] + bc1));
                }
                gr += 8;
                if (gr < n) {
                    unsigned* srow = seg + (size_t)ids[lr + 8] * 512;
                    atomicMax(&srow[col], fenc(acc[mf][nf][2] + bc0));
                    atomicMax(&srow[col + 1], fenc(acc[mf][nf][3] + bc1));
                }
            }
        }
    }
}

// ---------------- occupancy marking ----------------
__global__ void mark_occ(const int* __restrict__ xy, int n) {
    int i = blockIdx.x * 256 + threadIdx.x;
    if (i < n) g_occ[xy[(size_t)i * 2] * GYD + xy[(size_t)i * 2 + 1]] = 1;
}

// ---------------- head (bf16x3): relu(max(seg)[NSEG,512] @ W5[512,32] + b5) ------------
// BM=128 BN=32 BK=32. 8 warps, warp tile 16x32.
__global__ void __launch_bounds__(256) head_bf16x3(
    const unsigned* __restrict__ seg, const int* __restrict__ occ,
    const float* __restrict__ WT5, const float* __restrict__ b5, float* __restrict__ out) {
    __shared__ unsigned Ahi[128 * ASTR];
    __shared__ unsigned Alo[128 * ASTR];
    __shared__ unsigned Bhi[32 * BSTR];
    __shared__ unsigned Blo[32 * BSTR];
    __shared__ int occs[128];
    __shared__ float b5s[32];

    const int tid = threadIdx.x;
    const int lane = tid & 31;
    const int wid = tid >> 5;
    const int row0 = blockIdx.x * 128;
    const int m0 = wid * 16;
    const int kp = lane & 3;
    const int lg = lane >> 2;

    if (tid < 128) occs[tid] = occ[row0 + tid];
    if (tid < 32) b5s[tid] = b5[tid];
    __syncthreads();

    float acc[4][4] = {};
    uint4 pa[4];
    float4 pb;

#pragma unroll
    for (int l = 0; l < 4; l++) {
        int idx = tid + l * 256;
        int row = idx >> 3, k4 = (idx & 7) * 4;
        pa[l] = *(const uint4*)&seg[(size_t)(row0 + row) * 512 + k4];
    }
    { int c = tid >> 3, k4 = (tid & 7) * 4;
      pb = *(const float4*)&WT5[(size_t)c * 512 + k4]; }

    for (int k0 = 0; k0 < 512; k0 += 32) {
#pragma unroll
        for (int l = 0; l < 4; l++) {
            int idx = tid + l * 256;
            int row = idx >> 3, k4 = (idx & 7) * 4;
            float x0, x1, x2, x3;
            if (occs[row]) {
                x0 = fdec(pa[l].x); x1 = fdec(pa[l].y); x2 = fdec(pa[l].z); x3 = fdec(pa[l].w);
            } else { x0 = x1 = x2 = x3 = 0.f; }
            unsigned h0, l0, h1, l1;
            split2(x0, x1, h0, l0);
            split2(x2, x3, h1, l1);
            int c0 = k4 >> 1;
            Ahi[row * ASTR + pcol(c0)] = h0;
            Ahi[row * ASTR + pcol(c0 + 1)] = h1;
            Alo[row * ASTR + pcol(c0)] = l0;
            Alo[row * ASTR + pcol(c0 + 1)] = l1;
        }
        { int c = tid >> 3, k4 = (tid & 7) * 4;
          unsigned h0, l0, h1, l1;
          split2(pb.x, pb.y, h0, l0);
          split2(pb.z, pb.w, h1, l1);
          int c0 = k4 >> 1;
          Bhi[c * BSTR + pcol(c0)] = h0;
          Bhi[c * BSTR + pcol(c0 + 1)] = h1;
          Blo[c * BSTR + pcol(c0)] = l0;
          Blo[c * BSTR + pcol(c0 + 1)] = l1; }
        __syncthreads();

        if (k0 + 32 < 512) {
#pragma unroll
            for (int l = 0; l < 4; l++) {
                int idx = tid + l * 256;
                int row = idx >> 3, k4 = (idx & 7) * 4;
                pa[l] = *(const uint4*)&seg[(size_t)(row0 + row) * 512 + k0 + 32 + k4];
            }
            { int c = tid >> 3, k4 = (tid & 7) * 4;
              pb = *(const float4*)&WT5[(size_t)c * 512 + k0 + 32 + k4]; }
        }

#pragma unroll
        for (int s = 0; s < 2; s++) {
            unsigned ahi[4], alo[4];
            int r = m0 + lg;
            uint2 h0 = *(const uint2*)&Ahi[r * ASTR + s * 8 + 2 * kp];
            uint2 h1 = *(const uint2*)&Ahi[(r + 8) * ASTR + s * 8 + 2 * kp];
            ahi[0] = h0.x; ahi[1] = h1.x; ahi[2] = h0.y; ahi[3] = h1.y;
            uint2 q0 = *(const uint2*)&Alo[r * ASTR + s * 8 + 2 * kp];
            uint2 q1 = *(const uint2*)&Alo[(r + 8) * ASTR + s * 8 + 2 * kp];
            alo[0] = q0.x; alo[1] = q1.x; alo[2] = q0.y; alo[3] = q1.y;
#pragma unroll
            for (int nf = 0; nf < 4; nf++) {
                int c = nf * 8 + lg;
                uint2 h = *(const uint2*)&Bhi[c * BSTR + s * 8 + 2 * kp];
                uint2 q = *(const uint2*)&Blo[c * BSTR + s * 8 + 2 * kp];
                unsigned bh[2] = {h.x, h.y}, bl[2] = {q.x, q.y};
                mma_bf16(acc[nf], ahi, bh);
                mma_bf16(acc[nf], ahi, bl);
                mma_bf16(acc[nf], alo, bh);
            }
        }
        __syncthreads();
    }

#pragma unroll
    for (int nf = 0; nf < 4; nf++) {
        int lr = m0 + lg;
        int col = nf * 8 + 2 * kp;
        int gr = row0 + lr;
        float v0 = occs[lr] ? fmaxf(acc[nf][0] + b5s[col], 0.f) : 0.f;
        float v1 = occs[lr] ? fmaxf(acc[nf][1] + b5s[col + 1], 0.f) : 0.f;
        out[(size_t)col * NSEG + gr] = v0;
        out[(size_t)(col + 1) * NSEG + gr] = v1;
        float v2 = occs[lr + 8] ? fmaxf(acc[nf][2] + b5s[col], 0.f) : 0.f;
        float v3 = occs[lr + 8] ? fmaxf(acc[nf][3] + b5s[col + 1], 0.f) : 0.f;
        out[(size_t)col * NSEG + gr + 8] = v2;
        out[(size_t)(col + 1) * NSEG + gr + 8] = v3;
    }
}

// ---------------- host orchestration ----------------
extern "C" void kernel_launch(void* const* d_in, const int* in_sizes, int n_in,
                              void* d_out, int out_size) {
    const float* pt   = (const float*)d_in[0];
    const int*   xy   = (const int*)d_in[1];
    const float* bn0g = (const float*)d_in[2];
    const float* bn0b = (const float*)d_in[3];
    const float* W1   = (const float*)d_in[4];
    const float* b1   = (const float*)d_in[5];
    const float* bn1g = (const float*)d_in[6];
    const float* bn1b = (const float*)d_in[7];
    const float* W2   = (const float*)d_in[8];
    const float* b2   = (const float*)d_in[9];
    const float* bn2g = (const float*)d_in[10];
    const float* bn2b = (const float*)d_in[11];
    const float* W3   = (const float*)d_in[12];
    const float* b3   = (const float*)d_in[13];
    const float* bn3g = (const float*)d_in[14];
    const float* bn3b = (const float*)d_in[15];
    const float* W4   = (const float*)d_in[16];
    const float* b4   = (const float*)d_in[17];
    const float* W5   = (const float*)d_in[18];
    const float* b5   = (const float*)d_in[19];

    int B = out_size / (NHD * NSEG);
    if (B < 1) B = 1;
    int n = in_sizes[0] / (B * 7);
    float invn = 1.f / (float)n;

    float *y1, *y2, *y3, *sum, *sq, *sc, *sh, *wt2, *wt3, *wt4, *wt5;
    unsigned* seg;
    int* occ;
    cudaGetSymbolAddress((void**)&y1, g_y1);
    cudaGetSymbolAddress((void**)&y2, g_y2);
    cudaGetSymbolAddress((void**)&y3, g_y3);
    cudaGetSymbolAddress((void**)&seg, g_seg);
    cudaGetSymbolAddress((void**)&occ, g_occ);
    cudaGetSymbolAddress((void**)&sum, g_sum);
    cudaGetSymbolAddress((void**)&sq, g_sq);
    cudaGetSymbolAddress((void**)&sc, g_scale);
    cudaGetSymbolAddress((void**)&sh, g_shift);
    cudaGetSymbolAddress((void**)&wt2, g_wt2);
    cudaGetSymbolAddress((void**)&wt3, g_wt3);
    cudaGetSymbolAddress((void**)&wt4, g_wt4);
    cudaGetSymbolAddress((void**)&wt5, g_wt5);

    // weight transposes (once per launch)
    transpose_w<<<(64 * 128 + 255) / 256, 256>>>(W2, wt2, 64, 128);
    transpose_w<<<(128 * 256 + 255) / 256, 256>>>(W3, wt3, 128, 256);
    transpose_w<<<(256 * 512 + 255) / 256, 256>>>(W4, wt4, 256, 512);
    transpose_w<<<(512 * 32 + 255) / 256, 256>>>(W5, wt5, 512, 32);

    int nb128 = (n + 127) / 128;

    for (int b = 0; b < B; b++) {
        const float* fea = pt + (size_t)b * n * 7;
        const int* xyb = xy + (size_t)b * n * 2;
        float* outb = (float*)d_out + (size_t)b * NHD * NSEG;

        clear_kernel<<<4096, 256>>>();

        // bn0 stats
        colstats_kernel<<<512, 224>>>(fea, n, 7, sum + 0, sq + 0);
        finalize_kernel<<<1, 32>>>(sum + 0, sq + 0, bn0g, bn0b, sc + 0, sh + 0, 7, invn);

        // layer 1: 7 -> 64 (fp32 SIMT)
        gemm1_kernel<<<(n + 255) / 256, 256>>>(fea, sc + 0, sh + 0, W1, b1, y1, n);
        colstats_kernel<<<512, 256>>>(y1, n, 64, sum + 7, sq + 7);
        finalize_kernel<<<1, 64>>>(sum + 7, sq + 7, bn1g, bn1b, sc + 7, sh + 7, 64, invn);

        // layer 2: 64 -> 128
        gemm_bf16x3<0><<<dim3(1, nb128), 256, 2 * 64 * sizeof(float)>>>(
            y1, 64, sc + 7, sh + 7, wt2, 128, b2, y2, nullptr, nullptr, n);
        colstats_kernel<<<512, 256>>>(y2, n, 128, sum + 71, sq + 71);
        finalize_kernel<<<1, 128>>>(sum + 71, sq + 71, bn2g, bn2b, sc + 71, sh + 71, 128, invn);

        // layer 3: 128 -> 256
        gemm_bf16x3<0><<<dim3(2, nb128), 256, 2 * 128 * sizeof(float)>>>(
            y2, 128, sc + 71, sh + 71, wt3, 256, b3, y3, nullptr, nullptr, n);
        colstats_kernel<<<512, 256>>>(y3, n, 256, sum + 199, sq + 199);
        finalize_kernel<<<2, 128>>>(sum + 199, sq + 199, bn3g, bn3b, sc + 199, sh + 199, 256, invn);

        // occupancy + layer 4 (256 -> 512) with fused segment-max scatter
        mark_occ<<<(n + 255) / 256, 256>>>(xyb, n);
        gemm_bf16x3<1><<<dim3(4, nb128), 256, 2 * 256 * sizeof(float)>>>(
            y3, 256, sc + 199, sh + 199, wt4, 512, b4, nullptr, xyb, seg, n);

        // head: 512 -> 32, masked, transposed write
        head_bf16x3<<<NSEG / 128, 256>>>(seg, occ, wt5, b5, outb);
    }
}

// round 12
// speedup vs baseline: 1.9047x; 1.9047x over previous
#include <cuda_runtime.h>
#include <cuda_bf16.h>
#include <cstdint>
#include <cstddef>

#define GXD 480
#define GYD 360
#define NSEG (GXD*GYD)
#define NHD 32
#define MAXN 122880
#define MAXB 2
#define EPSF 1e-5f

__device__ float    g_y1[(size_t)MAXB * MAXN * 64];
__device__ float    g_y2[(size_t)MAXB * MAXN * 128];
__device__ float    g_y3[(size_t)MAXB * MAXN * 256];
__device__ unsigned g_seg[(size_t)MAXB * NSEG * 512];
__device__ int      g_occ[MAXB * NSEG];
__device__ float    g_sum[MAXB * 512];
__device__ float    g_sq[MAXB * 512];
__device__ float    g_scale[MAXB * 512];
__device__ float    g_shift[MAXB * 512];
// pre-split permuted weight planes [CO][K/2] u32 (bf16x2)
__device__ unsigned g_p2h[128 * 32],  g_p2l[128 * 32];
__device__ unsigned g_p3h[256 * 64],  g_p3l[256 * 64];
__device__ unsigned g_p4h[512 * 128], g_p4l[512 * 128];
__device__ unsigned g_p5h[32 * 256],  g_p5l[32 * 256];

__device__ __forceinline__ unsigned fenc(float f) {
    unsigned u = __float_as_uint(f);
    return (u & 0x80000000u) ? ~u : (u | 0x80000000u);
}
__device__ __forceinline__ float fdec(unsigned k) {
    unsigned u = (k & 0x80000000u) ? (k & 0x7FFFFFFFu) : ~k;
    return __uint_as_float(u);
}
__device__ __forceinline__ unsigned packbf(float x, float y) {
    __nv_bfloat162 t = __floats2bfloat162_rn(x, y);
    return *(unsigned*)&t;
}
__device__ __forceinline__ void split2(float x, float y, unsigned& hi, unsigned& lo) {
    __nv_bfloat16 hx = __float2bfloat16_rn(x);
    __nv_bfloat16 hy = __float2bfloat16_rn(y);
    hi = packbf(__bfloat162float(hx), __bfloat162float(hy));
    lo = packbf(x - __bfloat162float(hx), y - __bfloat162float(hy));
}
__device__ __forceinline__ void mma_bf16(float c[4], const unsigned a[4], const unsigned b[2]) {
    asm volatile(
        "mma.sync.aligned.m16n8k16.row.col.f32.bf16.bf16.f32 "
        "{%0,%1,%2,%3}, {%4,%5,%6,%7}, {%8,%9}, {%0,%1,%2,%3};"
        : "+f"(c[0]), "+f"(c[1]), "+f"(c[2]), "+f"(c[3])
        : "r"(a[0]), "r"(a[1]), "r"(a[2]), "r"(a[3]), "r"(b[0]), "r"(b[1]));
}
__device__ __forceinline__ int pcol(int c) {  // permute within 8-u32 group
    int cl = c & 7;
    return (c & ~7) | ((cl < 4) ? (2 * cl) : (2 * (cl - 4) + 1));
}
__device__ __forceinline__ uint32_t smem_u32(const void* p) {
    uint32_t a;
    asm("{ .reg .u64 t; cvta.to.shared.u64 t, %1; cvt.u32.u64 %0, t; }" : "=r"(a) : "l"(p));
    return a;
}
#define CP16(dst, src) \
    asm volatile("cp.async.cg.shared.global [%0], [%1], 16;" :: "r"(dst), "l"(src))
#define CPCOMMIT() asm volatile("cp.async.commit_group;" ::: "memory")
#define CPWAIT0()  asm volatile("cp.async.wait_group 0;" ::: "memory")

__global__ void clear_kernel(int B) {
    size_t i = (size_t)blockIdx.x * 256 + threadIdx.x;
    size_t stride = (size_t)gridDim.x * 256;
    size_t n4 = (size_t)B * NSEG * 512 / 4;
    uint4 zz = {0u, 0u, 0u, 0u};
    for (size_t j = i; j < n4; j += stride) ((uint4*)g_seg)[j] = zz;
    for (size_t j = i; j < (size_t)B * NSEG; j += stride) g_occ[j] = 0;
}

__global__ void prep_kernel(const float* __restrict__ W2, const float* __restrict__ W3,
                            const float* __restrict__ W4, const float* __restrict__ W5) {
    int i = blockIdx.x * 256 + threadIdx.x;
    if (i < MAXB * 512) { g_sum[i] = 0.f; g_sq[i] = 0.f; }
    int idx = i;
    unsigned h, l;
    if (idx < 4096) {  // W2 K=64 CO=128
        int c = idx >> 5, k2 = idx & 31;
        split2(W2[(2 * k2) * 128 + c], W2[(2 * k2 + 1) * 128 + c], h, l);
        g_p2h[c * 32 + pcol(k2)] = h; g_p2l[c * 32 + pcol(k2)] = l;
        return;
    }
    idx -= 4096;
    if (idx < 16384) {  // W3 K=128 CO=256
        int c = idx >> 6, k2 = idx & 63;
        split2(W3[(2 * k2) * 256 + c], W3[(2 * k2 + 1) * 256 + c], h, l);
        g_p3h[c * 64 + pcol(k2)] = h; g_p3l[c * 64 + pcol(k2)] = l;
        return;
    }
    idx -= 16384;
    if (idx < 65536) {  // W4 K=256 CO=512
        int c = idx >> 7, k2 = idx & 127;
        split2(W4[(2 * k2) * 512 + c], W4[(2 * k2 + 1) * 512 + c], h, l);
        g_p4h[c * 128 + pcol(k2)] = h; g_p4l[c * 128 + pcol(k2)] = l;
        return;
    }
    idx -= 65536;
    if (idx < 8192) {  // W5 K=512 CO=32
        int c = idx >> 8, k2 = idx & 255;
        split2(W5[(2 * k2) * 32 + c], W5[(2 * k2 + 1) * 32 + c], h, l);
        g_p5h[c * 256 + pcol(k2)] = h; g_p5l[c * 256 + pcol(k2)] = l;
    }
}

__global__ void colstats_kernel(const float* __restrict__ Xb, int n, int C,
                                float* __restrict__ gsum, float* __restrict__ gsq, int off) {
    int z = blockIdx.y;
    const float* X = Xb + (size_t)z * n * C;
    int tid = threadIdx.x, nt = blockDim.x;
    int col = tid % C, rpb = nt / C, sub = tid / C;
    float s = 0.f, q = 0.f;
    for (long long r = (long long)blockIdx.x * rpb + sub; r < n; r += (long long)gridDim.x * rpb) {
        float v = X[r * (long long)C + col];
        s += v; q += v * v;
    }
    __shared__ float ss[256], qq[256];
    ss[tid] = s; qq[tid] = q;
    __syncthreads();
    if (sub == 0) {
        for (int t = tid + C; t < nt; t += C) { s += ss[t]; q += qq[t]; }
        atomicAdd(&gsum[z * 512 + off + col], s);
        atomicAdd(&gsq[z * 512 + off + col], q);
    }
}

__global__ void finalize_kernel(const float* __restrict__ sum, const float* __restrict__ sq,
                                const float* __restrict__ g, const float* __restrict__ b,
                                float* __restrict__ scale, float* __restrict__ shift,
                                int C, int off, float invn) {
    int z = blockIdx.y;
    int i = blockIdx.x * 128 + threadIdx.x;
    if (i < C) {
        float m = sum[z * 512 + off + i] * invn;
        float v = sq[z * 512 + off + i] * invn - m * m;
        float sc = g[i] * rsqrtf(v + EPSF);
        scale[z * 512 + off + i] = sc;
        shift[z * 512 + off + i] = b[i] - m * sc;
    }
}

// layer1: [n,7]->[n,64] fp32 SIMT + fused y1 colstats (offset 7)
__global__ void __launch_bounds__(256) gemm1_kernel(
    const float* __restrict__ pt, const float* __restrict__ scb, const float* __restrict__ shb,
    const float* __restrict__ W, const float* __restrict__ bias,
    float* __restrict__ y1b, float* __restrict__ gsum, float* __restrict__ gsq, int n) {
    __shared__ float Ws[7][64], bs[64], scs[7], shs[7], ssum[64], ssq[64];
    int tid = threadIdx.x, lane = tid & 31;
    int z = blockIdx.y;
    const float* X = pt + (size_t)z * n * 7;
    float* Y = y1b + (size_t)z * n * 64;
    for (int i = tid; i < 448; i += 256) Ws[i / 64][i % 64] = W[i];
    if (tid < 64) { bs[tid] = bias[tid]; ssum[tid] = 0.f; ssq[tid] = 0.f; }
    if (tid < 7) { scs[tid] = scb[z * 512 + tid]; shs[tid] = shb[z * 512 + tid]; }
    __syncthreads();
    int r = blockIdx.x * 256 + tid;
    float acc[64];
    if (r < n) {
        float a[7];
#pragma unroll
        for (int f = 0; f < 7; f++) a[f] = X[(size_t)r * 7 + f] * scs[f] + shs[f];
#pragma unroll
        for (int c = 0; c < 64; c++) {
            float v = bs[c];
#pragma unroll
            for (int f = 0; f < 7; f++) v += a[f] * Ws[f][c];
            acc[c] = v;
        }
        float4* yo = (float4*)&Y[(size_t)r * 64];
#pragma unroll
        for (int c4 = 0; c4 < 16; c4++)
            yo[c4] = make_float4(acc[c4 * 4], acc[c4 * 4 + 1], acc[c4 * 4 + 2], acc[c4 * 4 + 3]);
    } else {
#pragma unroll
        for (int c = 0; c < 64; c++) acc[c] = 0.f;
    }
#pragma unroll
    for (int c = 0; c < 64; c++) {
        float v = acc[c], q = v * v;
#pragma unroll
        for (int d = 1; d < 32; d <<= 1) {
            v += __shfl_xor_sync(0xFFFFFFFFu, v, d);
            q += __shfl_xor_sync(0xFFFFFFFFu, q, d);
        }
        if (lane == 0) { atomicAdd(&ssum[c], v); atomicAdd(&ssq[c], q); }
    }
    __syncthreads();
    if (tid < 64) {
        atomicAdd(&gsum[z * 512 + 7 + tid], ssum[tid]);
        atomicAdd(&gsq[z * 512 + 7 + tid], ssq[tid]);
    }
}

__global__ void mark_occ(const int* __restrict__ xy, int n) {
    int z = blockIdx.y;
    int i = blockIdx.x * 256 + threadIdx.x;
    if (i < n) {
        const int* p = xy + (size_t)z * n * 2 + (size_t)i * 2;
        g_occ[z * NSEG + p[0] * GYD + p[1]] = 1;
    }
}

// ===== bf16x3 mma.sync GEMM: BM=128 BN=128 BK=32, double-buffered, cp.async B =====
#define STG     40960
#define OFF_DYN 81920
#define OFF_IDS 83968
#define OFF_CS  84480
#define GSM     85504

template <int EPI>
__global__ void __launch_bounds__(256, 2) gemm_fast(
    const float* __restrict__ Xb, int K, int nc, int CO,
    const float* __restrict__ scaleb, const float* __restrict__ shiftb,
    const unsigned* __restrict__ PBh, const unsigned* __restrict__ PBl,
    const float* __restrict__ bias,
    float* __restrict__ Yb, float* __restrict__ gsum, float* __restrict__ gsq,
    const int* __restrict__ xy, unsigned* __restrict__ segb, int n) {
    extern __shared__ __align__(16) char dsm[];
    const int tid = threadIdx.x, lane = tid & 31, wid = tid >> 5;
    const int z = blockIdx.z;
    const int row0 = blockIdx.y * 128, col0 = blockIdx.x * 128;
    const int m0 = (wid & 1) * 64, n0 = (wid >> 1) * 32, kp = lane & 3, lg = lane >> 2;
    const int K2 = K >> 1;
    const float* X = Xb + (size_t)z * n * K;
    float* scs = (float*)(dsm + OFF_DYN);
    float* shs = scs + K;
    int* ids = (int*)(dsm + OFF_IDS);
    // B-loader indices: 256 work items = 128 cols x 2 half-chunks
    const int bc = tid >> 1, bq = (tid & 1) * 8;

    for (int i = tid; i < K; i += 256) {
        scs[i] = scaleb[z * 512 + i];
        shs[i] = shiftb[z * 512 + i];
    }
    if (EPI == 1 && tid < 128) {
        int gr = row0 + tid;
        ids[tid] = (gr < n) ? (xy[(size_t)z * n * 2 + (size_t)gr * 2] * GYD +
                               xy[(size_t)z * n * 2 + (size_t)gr * 2 + 1]) : 0;
    }
    __syncthreads();

    float acc[4][4][4] = {};
    float4 pa[4];
#pragma unroll
    for (int l = 0; l < 4; l++) {
        int idx = tid + l * 256;
        int row = idx >> 3, k4 = (idx & 7) * 4;
        int gr = row0 + row;
        pa[l] = (gr < n) ? *(const float4*)&X[(size_t)gr * K + k4] : make_float4(0.f, 0.f, 0.f, 0.f);
    }
    {
        uint32_t b0 = smem_u32(dsm);
        const unsigned* sh_ = PBh + (size_t)(col0 + bc) * K2 + bq;
        const unsigned* sl_ = PBl + (size_t)(col0 + bc) * K2 + bq;
        uint32_t dh = b0 + 20480 + (bc * 20 + bq) * 4;
        uint32_t dl = b0 + 30720 + (bc * 20 + bq) * 4;
        CP16(dh, sh_); CP16(dh + 16, sh_ + 4);
        CP16(dl, sl_); CP16(dl + 16, sl_ + 4);
        CPCOMMIT();
    }

    for (int i = 0; i < nc; i++) {
        char* stb = dsm + (i & 1) * STG;
        unsigned* Ah = (unsigned*)stb;
        unsigned* Al = (unsigned*)(stb + 10240);
        unsigned* Bh = (unsigned*)(stb + 20480);
        unsigned* Bl = (unsigned*)(stb + 30720);
        int k0 = i * 32;
#pragma unroll
        for (int l = 0; l < 4; l++) {
            int idx = tid + l * 256;
            int row = idx >> 3, k4 = (idx & 7) * 4;
            float4 v = pa[l];
            float x0 = fmaxf(v.x * scs[k0 + k4 + 0] + shs[k0 + k4 + 0], 0.f);
            float x1 = fmaxf(v.y * scs[k0 + k4 + 1] + shs[k0 + k4 + 1], 0.f);
            float x2 = fmaxf(v.z * scs[k0 + k4 + 2] + shs[k0 + k4 + 2], 0.f);
            float x3 = fmaxf(v.w * scs[k0 + k4 + 3] + shs[k0 + k4 + 3], 0.f);
            unsigned h0, w0, h1, w1;
            split2(x0, x1, h0, w0);
            split2(x2, x3, h1, w1);
            int c0 = k4 >> 1;
            Ah[row * 20 + pcol(c0)] = h0; Ah[row * 20 + pcol(c0 + 1)] = h1;
            Al[row * 20 + pcol(c0)] = w0; Al[row * 20 + pcol(c0 + 1)] = w1;
        }
        CPWAIT0();
        __syncthreads();
        if (i + 1 < nc) {
            int k0n = k0 + 32;
#pragma unroll
            for (int l = 0; l < 4; l++) {
                int idx = tid + l * 256;
                int row = idx >> 3, k4 = (idx & 7) * 4;
                int gr = row0 + row;
                pa[l] = (gr < n) ? *(const float4*)&X[(size_t)gr * K + k0n + k4]
                                 : make_float4(0.f, 0.f, 0.f, 0.f);
            }
            uint32_t nb = smem_u32(dsm) + ((i + 1) & 1) * STG;
            const unsigned* sh_ = PBh + (size_t)(col0 + bc) * K2 + (k0n >> 1) + bq;
            const unsigned* sl_ = PBl + (size_t)(col0 + bc) * K2 + (k0n >> 1) + bq;
            uint32_t dh = nb + 20480 + (bc * 20 + bq) * 4;
            uint32_t dl = nb + 30720 + (bc * 20 + bq) * 4;
            CP16(dh, sh_); CP16(dh + 16, sh_ + 4);
            CP16(dl, sl_); CP16(dl + 16, sl_ + 4);
            CPCOMMIT();
        }
#pragma unroll
        for (int s = 0; s < 2; s++) {
            unsigned ahi[4][4], alo[4][4];
#pragma unroll
            for (int mf = 0; mf < 4; mf++) {
                int r = m0 + mf * 16 + lg;
                uint2 h0 = *(const uint2*)&Ah[r * 20 + s * 8 + 2 * kp];
                uint2 h1 = *(const uint2*)&Ah[(r + 8) * 20 + s * 8 + 2 * kp];
                ahi[mf][0] = h0.x; ahi[mf][1] = h1.x; ahi[mf][2] = h0.y; ahi[mf][3] = h1.y;
                uint2 q0 = *(const uint2*)&Al[r * 20 + s * 8 + 2 * kp];
                uint2 q1 = *(const uint2*)&Al[(r + 8) * 20 + s * 8 + 2 * kp];
                alo[mf][0] = q0.x; alo[mf][1] = q1.x; alo[mf][2] = q0.y; alo[mf][3] = q1.y;
            }
            unsigned bhi[4][2], blo[4][2];
#pragma unroll
            for (int nf = 0; nf < 4; nf++) {
                int c = n0 + nf * 8 + lg;
                uint2 h = *(const uint2*)&Bh[c * 20 + s * 8 + 2 * kp];
                bhi[nf][0] = h.x; bhi[nf][1] = h.y;
                uint2 q = *(const uint2*)&Bl[c * 20 + s * 8 + 2 * kp];
                blo[nf][0] = q.x; blo[nf][1] = q.y;
            }
#pragma unroll
            for (int mf = 0; mf < 4; mf++)
#pragma unroll
                for (int nf = 0; nf < 4; nf++) {
                    mma_bf16(acc[mf][nf], ahi[mf], bhi[nf]);
                    mma_bf16(acc[mf][nf], ahi[mf], blo[nf]);
                    mma_bf16(acc[mf][nf], alo[mf], bhi[nf]);
                }
        }
    }

    if (EPI == 0) {
        float* colsum = (float*)(dsm + OFF_CS);
        float* colsq = colsum + 128;
        __syncthreads();
        if (tid < 128) { colsum[tid] = 0.f; colsq[tid] = 0.f; }
        __syncthreads();
        float* Y = Yb + (size_t)z * n * CO;
#pragma unroll
        for (int nf = 0; nf < 4; nf++) {
            float cs0 = 0.f, cq0 = 0.f, cs1 = 0.f, cq1 = 0.f;
            int col = col0 + n0 + nf * 8 + 2 * kp;
            float bc0 = __ldg(&bias[col]), bc1 = __ldg(&bias[col + 1]);
#pragma unroll
            for (int mf = 0; mf < 4; mf++) {
                int gr = row0 + m0 + mf * 16 + lg;
                if (gr < n) {
                    float v0 = acc[mf][nf][0] + bc0, v1 = acc[mf][nf][1] + bc1;
                    *(float2*)&Y[(size_t)gr * CO + col] = make_float2(v0, v1);
                    cs0 += v0; cq0 += v0 * v0; cs1 += v1; cq1 += v1 * v1;
                }
                if (gr + 8 < n) {
                    float v2 = acc[mf][nf][2] + bc0, v3 = acc[mf][nf][3] + bc1;
                    *(float2*)&Y[(size_t)(gr + 8) * CO + col] = make_float2(v2, v3);
                    cs0 += v2; cq0 += v2 * v2; cs1 += v3; cq1 += v3 * v3;
                }
            }
#pragma unroll
            for (int d = 4; d <= 16; d <<= 1) {
                cs0 += __shfl_xor_sync(0xFFFFFFFFu, cs0, d);
                cq0 += __shfl_xor_sync(0xFFFFFFFFu, cq0, d);
                cs1 += __shfl_xor_sync(0xFFFFFFFFu, cs1, d);
                cq1 += __shfl_xor_sync(0xFFFFFFFFu, cq1, d);
            }
            if (lg == 0) {
                int cl = n0 + nf * 8 + 2 * kp;
                atomicAdd(&colsum[cl], cs0); atomicAdd(&colsq[cl], cq0);
                atomicAdd(&colsum[cl + 1], cs1); atomicAdd(&colsq[cl + 1], cq1);
            }
        }
        __syncthreads();
        if (tid < 128) {
            atomicAdd(&gsum[z * 512 + col0 + tid], colsum[tid]);
            atomicAdd(&gsq[z * 512 + col0 + tid], colsq[tid]);
        }
    } else {
        unsigned* seg = segb + (size_t)z * NSEG * 512;
#pragma unroll
        for (int mf = 0; mf < 4; mf++) {
#pragma unroll
            for (int nf = 0; nf < 4; nf++) {
                int lr = m0 + mf * 16 + lg;
                int col = col0 + n0 + nf * 8 + 2 * kp;
                float bc0 = __ldg(&bias[col]), bc1 = __ldg(&bias[col + 1]);
                int gr = row0 + lr;
                if (gr < n) {
                    unsigned* sr = seg + (size_t)ids[lr] * 512;
                    atomicMax(&sr[col], fenc(acc[mf][nf][0] + bc0));
                    atomicMax(&sr[col + 1], fenc(acc[mf][nf][1] + bc1));
                }
                if (gr + 8 < n) {
                    unsigned* sr = seg + (size_t)ids[lr + 8] * 512;
                    atomicMax(&sr[col], fenc(acc[mf][nf][2] + bc0));
                    atomicMax(&sr[col + 1], fenc(acc[mf][nf][3] + bc1));
                }
            }
        }
    }
}

// ===== head: relu(max(seg)[NSEG,512] @ W5 + b5), bf16x3, early-out, transposed write =====
__global__ void __launch_bounds__(256) head_fast(
    const unsigned* __restrict__ segb, const int* __restrict__ occb,
    const unsigned* __restrict__ PBh, const unsigned* __restrict__ PBl,
    const float* __restrict__ b5, float* __restrict__ outb) {
    __shared__ unsigned Ah[2560], Al[2560], Bh[640], Bl[640];
    __shared__ int occs[128];
    __shared__ float b5s[32];
    const int tid = threadIdx.x, lane = tid & 31, wid = tid >> 5;
    const int z = blockIdx.z;
    const int row0 = blockIdx.x * 128;
    const unsigned* seg = segb + (size_t)z * NSEG * 512;
    float* out = outb + (size_t)z * NHD * NSEG;

    int my = (tid < 128) ? occb[z * NSEG + row0 + tid] : 0;
    if (tid < 128) occs[tid] = my;
    if (tid < 32) b5s[tid] = b5[tid];
    int any = __syncthreads_or(my);
    if (!any) {
        for (int idx = tid; idx < 128 * NHD; idx += 256) {
            int c = idx >> 7, r = idx & 127;
            out[(size_t)c * NSEG + row0 + r] = 0.f;
        }
        return;
    }

    const int m0 = wid * 16, kp = lane & 3, lg = lane >> 2;
    float acc[4][4] = {};
    uint4 pa[4];
#pragma unroll
    for (int l = 0; l < 4; l++) {
        int idx = tid + l * 256;
        int row = idx >> 3, k4 = (idx & 7) * 4;
        pa[l] = *(const uint4*)&seg[(size_t)(row0 + row) * 512 + k4];
    }

    for (int k0 = 0; k0 < 512; k0 += 32) {
#pragma unroll
        for (int l = 0; l < 4; l++) {
            int idx = tid + l * 256;
            int row = idx >> 3, k4 = (idx & 7) * 4;
            float x0 = 0.f, x1 = 0.f, x2 = 0.f, x3 = 0.f;
            if (occs[row]) {
                x0 = fdec(pa[l].x); x1 = fdec(pa[l].y); x2 = fdec(pa[l].z); x3 = fdec(pa[l].w);
            }
            unsigned h0, w0, h1, w1;
            split2(x0, x1, h0, w0);
            split2(x2, x3, h1, w1);
            int c0 = k4 >> 1;
            Ah[row * 20 + pcol(c0)] = h0; Ah[row * 20 + pcol(c0 + 1)] = h1;
            Al[row * 20 + pcol(c0)] = w0; Al[row * 20 + pcol(c0 + 1)] = w1;
        }
        {
            int c = tid >> 3, q = (tid & 7) * 2;
            *(uint2*)&Bh[c * 20 + q] = *(const uint2*)&PBh[(size_t)c * 256 + (k0 >> 1) + q];
            *(uint2*)&Bl[c * 20 + q] = *(const uint2*)&PBl[(size_t)c * 256 + (k0 >> 1) + q];
        }
        __syncthreads();
        if (k0 + 32 < 512) {
#pragma unroll
            for (int l = 0; l < 4; l++) {
                int idx = tid + l * 256;
                int row = idx >> 3, k4 = (idx & 7) * 4;
                pa[l] = *(const uint4*)&seg[(size_t)(row0 + row) * 512 + k0 + 32 + k4];
            }
        }
#pragma unroll
        for (int s = 0; s < 2; s++) {
            unsigned ahi[4], alo[4];
            int r = m0 + lg;
            uint2 h0 = *(const uint2*)&Ah[r * 20 + s * 8 + 2 * kp];
            uint2 h1 = *(const uint2*)&Ah[(r + 8) * 20 + s * 8 + 2 * kp];
            ahi[0] = h0.x; ahi[1] = h1.x; ahi[2] = h0.y; ahi[3] = h1.y;
            uint2 q0 = *(const uint2*)&Al[r * 20 + s * 8 + 2 * kp];
            uint2 q1 = *(const uint2*)&Al[(r + 8) * 20 + s * 8 + 2 * kp];
            alo[0] = q0.x; alo[1] = q1.x; alo[2] = q0.y; alo[3] = q1.y;
#pragma unroll
            for (int nf = 0; nf < 4; nf++) {
                int c = nf * 8 + lg;
                uint2 h = *(const uint2*)&Bh[c * 20 + s * 8 + 2 * kp];
                uint2 w = *(const uint2*)&Bl[c * 20 + s * 8 + 2 * kp];
                unsigned bh[2] = {h.x, h.y}, bl[2] = {w.x, w.y};
                mma_bf16(acc[nf], ahi, bh);
                mma_bf16(acc[nf], ahi, bl);
                mma_bf16(acc[nf], alo, bh);
            }
        }
        __syncthreads();
    }

#pragma unroll
    for (int nf = 0; nf < 4; nf++) {
        int lr = m0 + lg, col = nf * 8 + 2 * kp, gr = row0 + lr;
        float v0 = occs[lr] ? fmaxf(acc[nf][0] + b5s[col], 0.f) : 0.f;
        float v1 = occs[lr] ? fmaxf(acc[nf][1] + b5s[col + 1], 0.f) : 0.f;
        out[(size_t)col * NSEG + gr] = v0;
        out[(size_t)(col + 1) * NSEG + gr] = v1;
        float v2 = occs[lr + 8] ? fmaxf(acc[nf][2] + b5s[col], 0.f) : 0.f;
        float v3 = occs[lr + 8] ? fmaxf(acc[nf][3] + b5s[col + 1], 0.f) : 0.f;
        out[(size_t)col * NSEG + gr + 8] = v2;
        out[(size_t)(col + 1) * NSEG + gr + 8] = v3;
    }
}

extern "C" void kernel_launch(void* const* d_in, const int* in_sizes, int n_in,
                              void* d_out, int out_size) {
    const float* pt   = (const float*)d_in[0];
    const int*   xy   = (const int*)d_in[1];
    const float* bn0g = (const float*)d_in[2];
    const float* bn0b = (const float*)d_in[3];
    const float* W1   = (const float*)d_in[4];
    const float* b1   = (const float*)d_in[5];
    const float* bn1g = (const float*)d_in[6];
    const float* bn1b = (const float*)d_in[7];
    const float* W2   = (const float*)d_in[8];
    const float* b2   = (const float*)d_in[9];
    const float* bn2g = (const float*)d_in[10];
    const float* bn2b = (const float*)d_in[11];
    const float* W3   = (const float*)d_in[12];
    const float* b3   = (const float*)d_in[13];
    const float* bn3g = (const float*)d_in[14];
    const float* bn3b = (const float*)d_in[15];
    const float* W4   = (const float*)d_in[16];
    const float* b4   = (const float*)d_in[17];
    const float* W5   = (const float*)d_in[18];
    const float* b5   = (const float*)d_in[19];

    int B = out_size / (NHD * NSEG);
    if (B < 1) B = 1;
    if (B > MAXB) B = MAXB;
    int n = in_sizes[0] / (B * 7);
    float invn = 1.f / (float)n;

    float *y1, *y2, *y3, *sum, *sq, *sc, *sh;
    unsigned *seg, *p2h, *p2l, *p3h, *p3l, *p4h, *p4l, *p5h, *p5l;
    int* occ;
    cudaGetSymbolAddress((void**)&y1, g_y1);
    cudaGetSymbolAddress((void**)&y2, g_y2);
    cudaGetSymbolAddress((void**)&y3, g_y3);
    cudaGetSymbolAddress((void**)&seg, g_seg);
    cudaGetSymbolAddress((void**)&occ, g_occ);
    cudaGetSymbolAddress((void**)&sum, g_sum);
    cudaGetSymbolAddress((void**)&sq, g_sq);
    cudaGetSymbolAddress((void**)&sc, g_scale);
    cudaGetSymbolAddress((void**)&sh, g_shift);
    cudaGetSymbolAddress((void**)&p2h, g_p2h);
    cudaGetSymbolAddress((void**)&p2l, g_p2l);
    cudaGetSymbolAddress((void**)&p3h, g_p3h);
    cudaGetSymbolAddress((void**)&p3l, g_p3l);
    cudaGetSymbolAddress((void**)&p4h, g_p4h);
    cudaGetSymbolAddress((void**)&p4l, g_p4l);
    cudaGetSymbolAddress((void**)&p5h, g_p5h);
    cudaGetSymbolAddress((void**)&p5l, g_p5l);

    cudaFuncSetAttribute(gemm_fast<0>, cudaFuncAttributeMaxDynamicSharedMemorySize, GSM);
    cudaFuncSetAttribute(gemm_fast<1>, cudaFuncAttributeMaxDynamicSharedMemorySize, GSM);

    int nb = (n + 127) / 128;

    clear_kernel<<<8192, 256>>>(B);
    prep_kernel<<<368, 256>>>(W2, W3, W4, W5);
    colstats_kernel<<<dim3(512, B), 224>>>(pt, n, 7, sum, sq, 0);
    finalize_kernel<<<dim3(1, B), 128>>>(sum, sq, bn0g, bn0b, sc, sh, 7, 0, invn);
    gemm1_kernel<<<dim3((n + 255) / 256, B), 256>>>(pt, sc, sh, W1, b1, y1, sum, sq, n);
    finalize_kernel<<<dim3(1, B), 128>>>(sum, sq, bn1g, bn1b, sc, sh, 64, 7, invn);
    gemm_fast<0><<<dim3(1, nb, B), 256, GSM>>>(
        y1, 64, 2, 128, sc + 7, sh + 7, p2h, p2l, b2, y2, sum + 71, sq + 71, nullptr, nullptr, n);
    finalize_kernel<<<dim3(1, B), 128>>>(sum, sq, bn2g, bn2b, sc, sh, 128, 71, invn);
    gemm_fast<0><<<dim3(2, nb, B), 256, GSM>>>(
        y2, 128, 4, 256, sc + 71, sh + 71, p3h, p3l, b3, y3, sum + 199, sq + 199, nullptr, nullptr, n);
    finalize_kernel<<<dim3(2, B), 128>>>(sum, sq, bn3g, bn3b, sc, sh, 256, 199, invn);
    mark_occ<<<dim3((n + 255) / 256, B), 256>>>(xy, n);
    gemm_fast<1><<<dim3(4, nb, B), 256, GSM>>>(
        y3, 256, 8, 512, sc + 199, sh + 199, p4h, p4l, b4, nullptr, nullptr, nullptr, xy, seg, n);
    head_fast<<<dim3(NSEG / 128, 1, B), 256>>>(seg, occ, p5h, p5l, b5, (float*)d_out);
}

// round 17
// speedup vs baseline: 2.0585x; 1.0807x over previous
#include <cuda_runtime.h>
#include <cuda_bf16.h>
#include <cstdint>
#include <cstddef>

#define GXD 480
#define GYD 360
#define NSEG (GXD*GYD)
#define NHD 32
#define MAXN 122880
#define MAXB 2
#define EPSF 1e-5f

__device__ float    g_y1[(size_t)MAXB * MAXN * 64];
__device__ float    g_y2[(size_t)MAXB * MAXN * 128];
__device__ float    g_y3[(size_t)MAXB * MAXN * 256];
__device__ unsigned g_seg[(size_t)MAXB * NSEG * 512];   // zero-init; invariant: all-zero at launch entry
__device__ int      g_occ[MAXB * NSEG];                 // same invariant
__device__ float    g_sum[MAXB * 512];
__device__ float    g_sq[MAXB * 512];
__device__ float    g_scale[MAXB * 512];
__device__ float    g_shift[MAXB * 512];
// pre-split permuted weight planes [CO][K/2] u32 (bf16x2)
__device__ unsigned g_p2h[128 * 32],  g_p2l[128 * 32];
__device__ unsigned g_p3h[256 * 64],  g_p3l[256 * 64];
__device__ unsigned g_p4h[512 * 128], g_p4l[512 * 128];
__device__ unsigned g_p5h[32 * 256],  g_p5l[32 * 256];

__device__ __forceinline__ unsigned fenc(float f) {
    unsigned u = __float_as_uint(f);
    return (u & 0x80000000u) ? ~u : (u | 0x80000000u);
}
__device__ __forceinline__ float fdec(unsigned k) {
    unsigned u = (k & 0x80000000u) ? (k & 0x7FFFFFFFu) : ~k;
    return __uint_as_float(u);
}
__device__ __forceinline__ unsigned packbf(float x, float y) {
    __nv_bfloat162 t = __floats2bfloat162_rn(x, y);
    return *(unsigned*)&t;
}
__device__ __forceinline__ void split2(float x, float y, unsigned& hi, unsigned& lo) {
    __nv_bfloat16 hx = __float2bfloat16_rn(x);
    __nv_bfloat16 hy = __float2bfloat16_rn(y);
    hi = packbf(__bfloat162float(hx), __bfloat162float(hy));
    lo = packbf(x - __bfloat162float(hx), y - __bfloat162float(hy));
}
__device__ __forceinline__ void mma_bf16(float c[4], const unsigned a[4], const unsigned b[2]) {
    asm volatile(
        "mma.sync.aligned.m16n8k16.row.col.f32.bf16.bf16.f32 "
        "{%0,%1,%2,%3}, {%4,%5,%6,%7}, {%8,%9}, {%0,%1,%2,%3};"
        : "+f"(c[0]), "+f"(c[1]), "+f"(c[2]), "+f"(c[3])
        : "r"(a[0]), "r"(a[1]), "r"(a[2]), "r"(a[3]), "r"(b[0]), "r"(b[1]));
}
__device__ __forceinline__ int pcol(int c) {  // permute within 8-u32 group
    int cl = c & 7;
    return (c & ~7) | ((cl < 4) ? (2 * cl) : (2 * (cl - 4) + 1));
}
__device__ __forceinline__ uint32_t smem_u32(const void* p) {
    uint32_t a;
    asm("{ .reg .u64 t; cvta.to.shared.u64 t, %1; cvt.u32.u64 %0, t; }" : "=r"(a) : "l"(p));
    return a;
}
#define CP16(dst, src) \
    asm volatile("cp.async.cg.shared.global [%0], [%1], 16;" :: "r"(dst), "l"(src))
#define CPCOMMIT() asm volatile("cp.async.commit_group;" ::: "memory")
#define CPWAIT0()  asm volatile("cp.async.wait_group 0;" ::: "memory")

__global__ void prep_kernel(const float* __restrict__ W2, const float* __restrict__ W3,
                            const float* __restrict__ W4, const float* __restrict__ W5) {
    int i = blockIdx.x * 256 + threadIdx.x;
    if (i < MAXB * 512) { g_sum[i] = 0.f; g_sq[i] = 0.f; }
    int idx = i;
    unsigned h, l;
    if (idx < 4096) {  // W2 K=64 CO=128
        int c = idx >> 5, k2 = idx & 31;
        split2(W2[(2 * k2) * 128 + c], W2[(2 * k2 + 1) * 128 + c], h, l);
        g_p2h[c * 32 + pcol(k2)] = h; g_p2l[c * 32 + pcol(k2)] = l;
        return;
    }
    idx -= 4096;
    if (idx < 16384) {  // W3 K=128 CO=256
        int c = idx >> 6, k2 = idx & 63;
        split2(W3[(2 * k2) * 256 + c], W3[(2 * k2 + 1) * 256 + c], h, l);
        g_p3h[c * 64 + pcol(k2)] = h; g_p3l[c * 64 + pcol(k2)] = l;
        return;
    }
    idx -= 16384;
    if (idx < 65536) {  // W4 K=256 CO=512
        int c = idx >> 7, k2 = idx & 127;
        split2(W4[(2 * k2) * 512 + c], W4[(2 * k2 + 1) * 512 + c], h, l);
        g_p4h[c * 128 + pcol(k2)] = h; g_p4l[c * 128 + pcol(k2)] = l;
        return;
    }
    idx -= 65536;
    if (idx < 8192) {  // W5 K=512 CO=32
        int c = idx >> 8, k2 = idx & 255;
        split2(W5[(2 * k2) * 32 + c], W5[(2 * k2 + 1) * 32 + c], h, l);
        g_p5h[c * 256 + pcol(k2)] = h; g_p5l[c * 256 + pcol(k2)] = l;
    }
}

__global__ void colstats_kernel(const float* __restrict__ Xb, int n, int C,
                                float* __restrict__ gsum, float* __restrict__ gsq, int off) {
    int z = blockIdx.y;
    const float* X = Xb + (size_t)z * n * C;
    int tid = threadIdx.x, nt = blockDim.x;
    int col = tid % C, rpb = nt / C, sub = tid / C;
    float s = 0.f, q = 0.f;
    for (long long r = (long long)blockIdx.x * rpb + sub; r < n; r += (long long)gridDim.x * rpb) {
        float v = X[r * (long long)C + col];
        s += v; q += v * v;
    }
    __shared__ float ss[256], qq[256];
    ss[tid] = s; qq[tid] = q;
    __syncthreads();
    if (sub == 0) {
        for (int t = tid + C; t < nt; t += C) { s += ss[t]; q += qq[t]; }
        atomicAdd(&gsum[z * 512 + off + col], s);
        atomicAdd(&gsq[z * 512 + off + col], q);
    }
}

__global__ void finalize_kernel(const float* __restrict__ sum, const float* __restrict__ sq,
                                const float* __restrict__ g, const float* __restrict__ b,
                                float* __restrict__ scale, float* __restrict__ shift,
                                int C, int off, float invn) {
    int z = blockIdx.y;
    int i = blockIdx.x * 128 + threadIdx.x;
    if (i < C) {
        float m = sum[z * 512 + off + i] * invn;
        float v = sq[z * 512 + off + i] * invn - m * m;
        float sc = g[i] * rsqrtf(v + EPSF);
        scale[z * 512 + off + i] = sc;
        shift[z * 512 + off + i] = b[i] - m * sc;
    }
}

// layer1: [n,7]->[n,64] fp32 SIMT + fused y1 colstats (offset 7)
__global__ void __launch_bounds__(256) gemm1_kernel(
    const float* __restrict__ pt, const float* __restrict__ scb, const float* __restrict__ shb,
    const float* __restrict__ W, const float* __restrict__ bias,
    float* __restrict__ y1b, float* __restrict__ gsum, float* __restrict__ gsq, int n) {
    __shared__ float Ws[7][64], bs[64], scs[7], shs[7], ssum[64], ssq[64];
    int tid = threadIdx.x, lane = tid & 31;
    int z = blockIdx.y;
    const float* X = pt + (size_t)z * n * 7;
    float* Y = y1b + (size_t)z * n * 64;
    for (int i = tid; i < 448; i += 256) Ws[i / 64][i % 64] = W[i];
    if (tid < 64) { bs[tid] = bias[tid]; ssum[tid] = 0.f; ssq[tid] = 0.f; }
    if (tid < 7) { scs[tid] = scb[z * 512 + tid]; shs[tid] = shb[z * 512 + tid]; }
    __syncthreads();
    int r = blockIdx.x * 256 + tid;
    float acc[64];
    if (r < n) {
        float a[7];
#pragma unroll
        for (int f = 0; f < 7; f++) a[f] = X[(size_t)r * 7 + f] * scs[f] + shs[f];
#pragma unroll
        for (int c = 0; c < 64; c++) {
            float v = bs[c];
#pragma unroll
            for (int f = 0; f < 7; f++) v += a[f] * Ws[f][c];
            acc[c] = v;
        }
        float4* yo = (float4*)&Y[(size_t)r * 64];
#pragma unroll
        for (int c4 = 0; c4 < 16; c4++)
            yo[c4] = make_float4(acc[c4 * 4], acc[c4 * 4 + 1], acc[c4 * 4 + 2], acc[c4 * 4 + 3]);
    } else {
#pragma unroll
        for (int c = 0; c < 64; c++) acc[c] = 0.f;
    }
#pragma unroll
    for (int c = 0; c < 64; c++) {
        float v = acc[c], q = v * v;
#pragma unroll
        for (int d = 1; d < 32; d <<= 1) {
            v += __shfl_xor_sync(0xFFFFFFFFu, v, d);
            q += __shfl_xor_sync(0xFFFFFFFFu, q, d);
        }
        if (lane == 0) { atomicAdd(&ssum[c], v); atomicAdd(&ssq[c], q); }
    }
    __syncthreads();
    if (tid < 64) {
        atomicAdd(&gsum[z * 512 + 7 + tid], ssum[tid]);
        atomicAdd(&gsq[z * 512 + 7 + tid], ssq[tid]);
    }
}

__global__ void mark_occ(const int* __restrict__ xy, int n) {
    int z = blockIdx.y;
    int i = blockIdx.x * 256 + threadIdx.x;
    if (i < n) {
        const int* p = xy + (size_t)z * n * 2 + (size_t)i * 2;
        g_occ[z * NSEG + p[0] * GYD + p[1]] = 1;
    }
}

// ===== bf16x3 mma.sync GEMM: BM=128 BN=128 BK=32, double-buffered, cp.async B =====
#define STG     40960
#define OFF_DYN 81920
#define OFF_IDS 83968
#define OFF_CS  84480
#define GSM     85504

template <int EPI>
__global__ void __launch_bounds__(256, 2) gemm_fast(
    const float* __restrict__ Xb, int K, int nc, int CO,
    const float* __restrict__ scaleb, const float* __restrict__ shiftb,
    const unsigned* __restrict__ PBh, const unsigned* __restrict__ PBl,
    const float* __restrict__ bias,
    float* __restrict__ Yb, float* __restrict__ gsum, float* __restrict__ gsq,
    const int* __restrict__ xy, unsigned* __restrict__ segb, int n) {
    extern __shared__ __align__(16) char dsm[];
    const int tid = threadIdx.x, lane = tid & 31, wid = tid >> 5;
    const int z = blockIdx.z;
    const int row0 = blockIdx.y * 128, col0 = blockIdx.x * 128;
    const int m0 = (wid & 1) * 64, n0 = (wid >> 1) * 32, kp = lane & 3, lg = lane >> 2;
    const int K2 = K >> 1;
    const float* X = Xb + (size_t)z * n * K;
    float* scs = (float*)(dsm + OFF_DYN);
    float* shs = scs + K;
    int* ids = (int*)(dsm + OFF_IDS);
    const int bc = tid >> 1, bq = (tid & 1) * 8;  // 256 items = 128 cols x 2 half-chunks

    for (int i = tid; i < K; i += 256) {
        scs[i] = scaleb[z * 512 + i];
        shs[i] = shiftb[z * 512 + i];
    }
    if (EPI == 1 && tid < 128) {
        int gr = row0 + tid;
        ids[tid] = (gr < n) ? (xy[(size_t)z * n * 2 + (size_t)gr * 2] * GYD +
                               xy[(size_t)z * n * 2 + (size_t)gr * 2 + 1]) : 0;
    }
    __syncthreads();

    float acc[4][4][4] = {};
    float4 pa[4];
#pragma unroll
    for (int l = 0; l < 4; l++) {
        int idx = tid + l * 256;
        int row = idx >> 3, k4 = (idx & 7) * 4;
        int gr = row0 + row;
        pa[l] = (gr < n) ? *(const float4*)&X[(size_t)gr * K + k4] : make_float4(0.f, 0.f, 0.f, 0.f);
    }
    {
        uint32_t b0 = smem_u32(dsm);
        const unsigned* sh_ = PBh + (size_t)(col0 + bc) * K2 + bq;
        const unsigned* sl_ = PBl + (size_t)(col0 + bc) * K2 + bq;
        uint32_t dh = b0 + 20480 + (bc * 20 + bq) * 4;
        uint32_t dl = b0 + 30720 + (bc * 20 + bq) * 4;
        CP16(dh, sh_); CP16(dh + 16, sh_ + 4);
        CP16(dl, sl_); CP16(dl + 16, sl_ + 4);
        CPCOMMIT();
    }

    for (int i = 0; i < nc; i++) {
        char* stb = dsm + (i & 1) * STG;
        unsigned* Ah = (unsigned*)stb;
        unsigned* Al = (unsigned*)(stb + 10240);
        unsigned* Bh = (unsigned*)(stb + 20480);
        unsigned* Bl = (unsigned*)(stb + 30720);
        int k0 = i * 32;
#pragma unroll
        for (int l = 0; l < 4; l++) {
            int idx = tid + l * 256;
            int row = idx >> 3, k4 = (idx & 7) * 4;
            float4 v = pa[l];
            float x0 = fmaxf(v.x * scs[k0 + k4 + 0] + shs[k0 + k4 + 0], 0.f);
            float x1 = fmaxf(v.y * scs[k0 + k4 + 1] + shs[k0 + k4 + 1], 0.f);
            float x2 = fmaxf(v.z * scs[k0 + k4 + 2] + shs[k0 + k4 + 2], 0.f);
            float x3 = fmaxf(v.w * scs[k0 + k4 + 3] + shs[k0 + k4 + 3], 0.f);
            unsigned h0, w0, h1, w1;
            split2(x0, x1, h0, w0);
            split2(x2, x3, h1, w1);
            int c0 = k4 >> 1;
            Ah[row * 20 + pcol(c0)] = h0; Ah[row * 20 + pcol(c0 + 1)] = h1;
            Al[row * 20 + pcol(c0)] = w0; Al[row * 20 + pcol(c0 + 1)] = w1;
        }
        CPWAIT0();
        __syncthreads();
        if (i + 1 < nc) {
            int k0n = k0 + 32;
#pragma unroll
            for (int l = 0; l < 4; l++) {
                int idx = tid + l * 256;
                int row = idx >> 3, k4 = (idx & 7) * 4;
                int gr = row0 + row;
                pa[l] = (gr < n) ? *(const float4*)&X[(size_t)gr * K + k0n + k4]
                                 : make_float4(0.f, 0.f, 0.f, 0.f);
            }
            uint32_t nb = smem_u32(dsm) + ((i + 1) & 1) * STG;
            const unsigned* sh_ = PBh + (size_t)(col0 + bc) * K2 + (k0n >> 1) + bq;
            const unsigned* sl_ = PBl + (size_t)(col0 + bc) * K2 + (k0n >> 1) + bq;
            uint32_t dh = nb + 20480 + (bc * 20 + bq) * 4;
            uint32_t dl = nb + 30720 + (bc * 20 + bq) * 4;
            CP16(dh, sh_); CP16(dh + 16, sh_ + 4);
            CP16(dl, sl_); CP16(dl + 16, sl_ + 4);
            CPCOMMIT();
        }
#pragma unroll
        for (int s = 0; s < 2; s++) {
            unsigned ahi[4][4], alo[4][4];
#pragma unroll
            for (int mf = 0; mf < 4; mf++) {
                int r = m0 + mf * 16 + lg;
                uint2 h0 = *(const uint2*)&Ah[r * 20 + s * 8 + 2 * kp];
                uint2 h1 = *(const uint2*)&Ah[(r + 8) * 20 + s * 8 + 2 * kp];
                ahi[mf][0] = h0.x; ahi[mf][1] = h1.x; ahi[mf][2] = h0.y; ahi[mf][3] = h1.y;
                uint2 q0 = *(const uint2*)&Al[r * 20 + s * 8 + 2 * kp];
                uint2 q1 = *(const uint2*)&Al[(r + 8) * 20 + s * 8 + 2 * kp];
                alo[mf][0] = q0.x; alo[mf][1] = q1.x; alo[mf][2] = q0.y; alo[mf][3] = q1.y;
            }
            unsigned bhi[4][2], blo[4][2];
#pragma unroll
            for (int nf = 0; nf < 4; nf++) {
                int c = n0 + nf * 8 + lg;
                uint2 h = *(const uint2*)&Bh[c * 20 + s * 8 + 2 * kp];
                bhi[nf][0] = h.x; bhi[nf][1] = h.y;
                uint2 q = *(const uint2*)&Bl[c * 20 + s * 8 + 2 * kp];
                blo[nf][0] = q.x; blo[nf][1] = q.y;
            }
#pragma unroll
            for (int mf = 0; mf < 4; mf++)
#pragma unroll
                for (int nf = 0; nf < 4; nf++) {
                    mma_bf16(acc[mf][nf], ahi[mf], bhi[nf]);
                    mma_bf16(acc[mf][nf], ahi[mf], blo[nf]);
                    mma_bf16(acc[mf][nf], alo[mf], bhi[nf]);
                }
        }
    }

    if (EPI == 0) {
        float* colsum = (float*)(dsm + OFF_CS);
        float* colsq = colsum + 128;
        __syncthreads();
        if (tid < 128) { colsum[tid] = 0.f; colsq[tid] = 0.f; }
        __syncthreads();
        float* Y = Yb + (size_t)z * n * CO;
#pragma unroll
        for (int nf = 0; nf < 4; nf++) {
            float cs0 = 0.f, cq0 = 0.f, cs1 = 0.f, cq1 = 0.f;
            int col = col0 + n0 + nf * 8 + 2 * kp;
            float bc0 = __ldg(&bias[col]), bc1 = __ldg(&bias[col + 1]);
#pragma unroll
            for (int mf = 0; mf < 4; mf++) {
                int gr = row0 + m0 + mf * 16 + lg;
                if (gr < n) {
                    float v0 = acc[mf][nf][0] + bc0, v1 = acc[mf][nf][1] + bc1;
                    *(float2*)&Y[(size_t)gr * CO + col] = make_float2(v0, v1);
                    cs0 += v0; cq0 += v0 * v0; cs1 += v1; cq1 += v1 * v1;
                }
                if (gr + 8 < n) {
                    float v2 = acc[mf][nf][2] + bc0, v3 = acc[mf][nf][3] + bc1;
                    *(float2*)&Y[(size_t)(gr + 8) * CO + col] = make_float2(v2, v3);
                    cs0 += v2; cq0 += v2 * v2; cs1 += v3; cq1 += v3 * v3;
                }
            }
#pragma unroll
            for (int d = 4; d <= 16; d <<= 1) {
                cs0 += __shfl_xor_sync(0xFFFFFFFFu, cs0, d);
                cq0 += __shfl_xor_sync(0xFFFFFFFFu, cq0, d);
                cs1 += __shfl_xor_sync(0xFFFFFFFFu, cs1, d);
                cq1 += __shfl_xor_sync(0xFFFFFFFFu, cq1, d);
            }
            if (lg == 0) {
                int cl = n0 + nf * 8 + 2 * kp;
                atomicAdd(&colsum[cl], cs0); atomicAdd(&colsq[cl], cq0);
                atomicAdd(&colsum[cl + 1], cs1); atomicAdd(&colsq[cl + 1], cq1);
            }
        }
        __syncthreads();
        if (tid < 128) {
            atomicAdd(&gsum[z * 512 + col0 + tid], colsum[tid]);
            atomicAdd(&gsq[z * 512 + col0 + tid], colsq[tid]);
        }
    } else {
        unsigned* seg = segb + (size_t)z * NSEG * 512;
#pragma unroll
        for (int mf = 0; mf < 4; mf++) {
#pragma unroll
            for (int nf = 0; nf < 4; nf++) {
                int lr = m0 + mf * 16 + lg;
                int col = col0 + n0 + nf * 8 + 2 * kp;
                float bc0 = __ldg(&bias[col]), bc1 = __ldg(&bias[col + 1]);
                int gr = row0 + lr;
                if (gr < n) {
                    unsigned* sr = seg + (size_t)ids[lr] * 512;
                    atomicMax(&sr[col], fenc(acc[mf][nf][0] + bc0));
                    atomicMax(&sr[col + 1], fenc(acc[mf][nf][1] + bc1));
                }
                if (gr + 8 < n) {
                    unsigned* sr = seg + (size_t)ids[lr + 8] * 512;
                    atomicMax(&sr[col], fenc(acc[mf][nf][2] + bc0));
                    atomicMax(&sr[col + 1], fenc(acc[mf][nf][3] + bc1));
                }
            }
        }
    }
}

// ===== head: relu(max(seg) @ W5 + b5) + seg/occ re-zero (maintains invariant) =====
__global__ void __launch_bounds__(256) head_fast(
    unsigned* __restrict__ segb, int* __restrict__ occb,
    const unsigned* __restrict__ PBh, const unsigned* __restrict__ PBl,
    const float* __restrict__ b5, float* __restrict__ outb) {
    __shared__ unsigned Ah[2560], Al[2560], Bh[640], Bl[640];
    __shared__ int occs[128];
    __shared__ float b5s[32];
    const int tid = threadIdx.x, lane = tid & 31, wid = tid >> 5;
    const int z = blockIdx.z;
    const int row0 = blockIdx.x * 128;
    unsigned* seg = segb + (size_t)z * NSEG * 512;
    float* out = outb + (size_t)z * NHD * NSEG;

    int my = (tid < 128) ? occb[z * NSEG + row0 + tid] : 0;
    if (tid < 128) occs[tid] = my;
    if (tid < 32) b5s[tid] = b5[tid];
    int any = __syncthreads_or(my);
    if (!any) {  // block untouched this replay: seg rows already zero, occ already zero
        for (int idx = tid; idx < 128 * NHD; idx += 256) {
            int c = idx >> 7, r = idx & 127;
            out[(size_t)c * NSEG + row0 + r] = 0.f;
        }
        return;
    }

    const int m0 = wid * 16, kp = lane & 3, lg = lane >> 2;
    float acc[4][4] = {};
    uint4 pa[4];
#pragma unroll
    for (int l = 0; l < 4; l++) {
        int idx = tid + l * 256;
        int row = idx >> 3, k4 = (idx & 7) * 4;
        pa[l] = occs[row] ? *(const uint4*)&seg[(size_t)(row0 + row) * 512 + k4]
                          : make_uint4(0u, 0u, 0u, 0u);
    }

    for (int k0 = 0; k0 < 512; k0 += 32) {
#pragma unroll
        for (int l = 0; l < 4; l++) {
            int idx = tid + l * 256;
            int row = idx >> 3, k4 = (idx & 7) * 4;
            float x0 = 0.f, x1 = 0.f, x2 = 0.f, x3 = 0.f;
            if (occs[row]) {
                x0 = fdec(pa[l].x); x1 = fdec(pa[l].y); x2 = fdec(pa[l].z); x3 = fdec(pa[l].w);
            }
            unsigned h0, w0, h1, w1;
            split2(x0, x1, h0, w0);
            split2(x2, x3, h1, w1);
            int c0 = k4 >> 1;
            Ah[row * 20 + pcol(c0)] = h0; Ah[row * 20 + pcol(c0 + 1)] = h1;
            Al[row * 20 + pcol(c0)] = w0; Al[row * 20 + pcol(c0 + 1)] = w1;
        }
        {
            int c = tid >> 3, q = (tid & 7) * 2;
            *(uint2*)&Bh[c * 20 + q] = *(const uint2*)&PBh[(size_t)c * 256 + (k0 >> 1) + q];
            *(uint2*)&Bl[c * 20 + q] = *(const uint2*)&PBl[(size_t)c * 256 + (k0 >> 1) + q];
        }
        __syncthreads();
        if (k0 + 32 < 512) {
#pragma unroll
            for (int l = 0; l < 4; l++) {
                int idx = tid + l * 256;
                int row = idx >> 3, k4 = (idx & 7) * 4;
                pa[l] = occs[row] ? *(const uint4*)&seg[(size_t)(row0 + row) * 512 + k0 + 32 + k4]
                                  : make_uint4(0u, 0u, 0u, 0u);
            }
        }
#pragma unroll
        for (int s = 0; s < 2; s++) {
            unsigned ahi[4], alo[4];
            int r = m0 + lg;
            uint2 h0 = *(const uint2*)&Ah[r * 20 + s * 8 + 2 * kp];
            uint2 h1 = *(const uint2*)&Ah[(r + 8) * 20 + s * 8 + 2 * kp];
            ahi[0] = h0.x; ahi[1] = h1.x; ahi[2] = h0.y; ahi[3] = h1.y;
            uint2 q0 = *(const uint2*)&Al[r * 20 + s * 8 + 2 * kp];
            uint2 q1 = *(const uint2*)&Al[(r + 8) * 20 + s * 8 + 2 * kp];
            alo[0] = q0.x; alo[1] = q1.x; alo[2] = q0.y; alo[3] = q1.y;
#pragma unroll
            for (int nf = 0; nf < 4; nf++) {
                int c = nf * 8 + lg;
                uint2 h = *(const uint2*)&Bh[c * 20 + s * 8 + 2 * kp];
                uint2 w = *(const uint2*)&Bl[c * 20 + s * 8 + 2 * kp];
                unsigned bh[2] = {h.x, h.y}, bl[2] = {w.x, w.y};
                mma_bf16(acc[nf], ahi, bh);
                mma_bf16(acc[nf], ahi, bl);
                mma_bf16(acc[nf], alo, bh);
            }
        }
        __syncthreads();   // all seg reads for this block complete after this barrier
    }

    // epilogue: occ-masked, transposed write
#pragma unroll
    for (int nf = 0; nf < 4; nf++) {
        int lr = m0 + lg, col = nf * 8 + 2 * kp, gr = row0 + lr;
        float v0 = occs[lr] ? fmaxf(acc[nf][0] + b5s[col], 0.f) : 0.f;
        float v1 = occs[lr] ? fmaxf(acc[nf][1] + b5s[col + 1], 0.f) : 0.f;
        out[(size_t)col * NSEG + gr] = v0;
        out[(size_t)(col + 1) * NSEG + gr] = v1;
        float v2 = occs[lr + 8] ? fmaxf(acc[nf][2] + b5s[col], 0.f) : 0.f;
        float v3 = occs[lr + 8] ? fmaxf(acc[nf][3] + b5s[col + 1], 0.f) : 0.f;
        out[(size_t)col * NSEG + gr + 8] = v2;
        out[(size_t)(col + 1) * NSEG + gr + 8] = v3;
    }

    // re-zero consumed seg rows + occ (invariant for next replay).
    // Safe: last seg reads happened before the final mainloop __syncthreads.
    uint4 zz = make_uint4(0u, 0u, 0u, 0u);
    for (int it = tid; it < 128 * 128; it += 256) {
        int row = it >> 7, c4 = (it & 127) * 4;
        if (occs[row]) *(uint4*)&seg[(size_t)(row0 + row) * 512 + c4] = zz;
    }
    if (tid < 128) occb[z * NSEG + row0 + tid] = 0;
}

extern "C" void kernel_launch(void* const* d_in, const int* in_sizes, int n_in,
                              void* d_out, int out_size) {
    const float* pt   = (const float*)d_in[0];
    const int*   xy   = (const int*)d_in[1];
    const float* bn0g = (const float*)d_in[2];
    const float* bn0b = (const float*)d_in[3];
    const float* W1   = (const float*)d_in[4];
    const float* b1   = (const float*)d_in[5];
    const float* bn1g = (const float*)d_in[6];
    const float* bn1b = (const float*)d_in[7];
    const float* W2   = (const float*)d_in[8];
    const float* b2   = (const float*)d_in[9];
    const float* bn2g = (const float*)d_in[10];
    const float* bn2b = (const float*)d_in[11];
    const float* W3   = (const float*)d_in[12];
    const float* b3   = (const float*)d_in[13];
    const float* bn3g = (const float*)d_in[14];
    const float* bn3b = (const float*)d_in[15];
    const float* W4   = (const float*)d_in[16];
    const float* b4   = (const float*)d_in[17];
    const float* W5   = (const float*)d_in[18];
    const float* b5   = (const float*)d_in[19];

    int B = out_size / (NHD * NSEG);
    if (B < 1) B = 1;
    if (B > MAXB) B = MAXB;
    int n = in_sizes[0] / (B * 7);
    float invn = 1.f / (float)n;

    float *y1, *y2, *y3, *sum, *sq, *sc, *sh;
    unsigned *seg, *p2h, *p2l, *p3h, *p3l, *p4h, *p4l, *p5h, *p5l;
    int* occ;
    cudaGetSymbolAddress((void**)&y1, g_y1);
    cudaGetSymbolAddress((void**)&y2, g_y2);
    cudaGetSymbolAddress((void**)&y3, g_y3);
    cudaGetSymbolAddress((void**)&seg, g_seg);
    cudaGetSymbolAddress((void**)&occ, g_occ);
    cudaGetSymbolAddress((void**)&sum, g_sum);
    cudaGetSymbolAddress((void**)&sq, g_sq);
    cudaGetSymbolAddress((void**)&sc, g_scale);
    cudaGetSymbolAddress((void**)&sh, g_shift);
    cudaGetSymbolAddress((void**)&p2h, g_p2h);
    cudaGetSymbolAddress((void**)&p2l, g_p2l);
    cudaGetSymbolAddress((void**)&p3h, g_p3h);
    cudaGetSymbolAddress((void**)&p3l, g_p3l);
    cudaGetSymbolAddress((void**)&p4h, g_p4h);
    cudaGetSymbolAddress((void**)&p4l, g_p4l);
    cudaGetSymbolAddress((void**)&p5h, g_p5h);
    cudaGetSymbolAddress((void**)&p5l, g_p5l);

    cudaFuncSetAttribute(gemm_fast<0>, cudaFuncAttributeMaxDynamicSharedMemorySize, GSM);
    cudaFuncSetAttribute(gemm_fast<1>, cudaFuncAttributeMaxDynamicSharedMemorySize, GSM);

    int nb = (n + 127) / 128;

    prep_kernel<<<368, 256>>>(W2, W3, W4, W5);
    colstats_kernel<<<dim3(512, B), 224>>>(pt, n, 7, sum, sq, 0);
    finalize_kernel<<<dim3(1, B), 128>>>(sum, sq, bn0g, bn0b, sc, sh, 7, 0, invn);
    gemm1_kernel<<<dim3((n + 255) / 256, B), 256>>>(pt, sc, sh, W1, b1, y1, sum, sq, n);
    finalize_kernel<<<dim3(1, B), 128>>>(sum, sq, bn1g, bn1b, sc, sh, 64, 7, invn);
    gemm_fast<0><<<dim3(1, nb, B), 256, GSM>>>(
        y1, 64, 2, 128, sc + 7, sh + 7, p2h, p2l, b2, y2, sum + 71, sq + 71, nullptr, nullptr, n);
    finalize_kernel<<<dim3(1, B), 128>>>(sum, sq, bn2g, bn2b, sc, sh, 128, 71, invn);
    gemm_fast<0><<<dim3(2, nb, B), 256, GSM>>>(
        y2, 128, 4, 256, sc + 71, sh + 71, p3h, p3l, b3, y3, sum + 199, sq + 199, nullptr, nullptr, n);
    finalize_kernel<<<dim3(2, B), 128>>>(sum, sq, bn3g, bn3b, sc, sh, 256, 199, invn);
    mark_occ<<<dim3((n + 255) / 256, B), 256>>>(xy, n);
    gemm_fast<1><<<dim3(4, nb, B), 256, GSM>>>(
        y3, 256, 8, 512, sc + 199, sh + 199, p4h, p4l, b4, nullptr, nullptr, nullptr, xy, seg, n);
    head_fast<<<dim3(NSEG / 128, 1, B), 256>>>(seg, occ, p5h, p5l, b5, (float*)d_out);
}